// round 13
// baseline (speedup 1.0000x reference)
#include <cuda_runtime.h>
#include <math.h>

// Shapes (hardcoded for this problem instance)
#define BB   2
#define HH   16
#define SS   2048
#define DD   128
#define MM   4096          // memories per head
#define QQ   4096          // B*S queries per head

#define TQ   64            // query tile per CTA (occ-2 sizing)
#define TM   128           // memory tile per iteration
#define NTHREADS 128

// SMEM (floats): Qs [d][q] 128x64 @0 (32KB), Ks [d][m] 128x128 @8192 (64KB)
// sims alias into Ks head: 64 rows x stride 129 = 8256 floats (33KB <= 64KB)
#define SMEM_FLOATS (8192 + 16384)

// Scratch: normalized tensors stored TRANSPOSED + PRE-SWIZZLED per tile block:
//   g_kt: [h][mt (32)][d (128)][perm8_d(r) (128)]   64KB blocks
//   g_qt: [h][qt (64)][d (128)][perm16_d(r) (64)]   32KB blocks
// perm8_d(r)  = ((r>>2 ^ ((d>>2)&7 )) << 2) | (r&3)
// perm16_d(r) = ((r>>2 ^ ((d>>2)&15)) << 2) | (r&3)
__device__ float g_kt[HH * MM * DD];
__device__ float g_qt[HH * QQ * DD];

// ---------------------------------------------------------------------------
// Norm + transpose + swizzle kernels: block = (h, 32-row chunk), 256 threads.
// Row normalization arithmetic identical to R1 (warp-per-row, shfl reduce).
// ---------------------------------------------------------------------------
__global__ void normT_k_kernel(const float* __restrict__ km) {
    __shared__ float tile[32][132];
    const int h     = blockIdx.y;
    const int chunk = blockIdx.x;       // rows chunk*32 .. +31
    const int tid   = threadIdx.x;
    const int w = tid >> 5, l = tid & 31;

    #pragma unroll
    for (int rr = 0; rr < 4; ++rr) {
        const int row = w * 4 + rr;     // 0..31
        const size_t grow = (size_t)(h * MM + chunk * 32 + row);
        float4 v = __ldg(((const float4*)(km + grow * DD)) + l);
        float ss = v.x * v.x + v.y * v.y + v.z * v.z + v.w * v.w;
        #pragma unroll
        for (int o = 16; o > 0; o >>= 1) ss += __shfl_xor_sync(0xffffffffu, ss, o);
        float inv = 1.0f / fmaxf(sqrtf(ss), 1e-11f);
        tile[row][l * 4 + 0] = v.x * inv;
        tile[row][l * 4 + 1] = v.y * inv;
        tile[row][l * 4 + 2] = v.z * inv;
        tile[row][l * 4 + 3] = v.w * inv;
    }
    __syncthreads();

    // write transposed + swizzled into the 64KB tile block
    float* blk = g_kt + ((size_t)(h * 32 + (chunk >> 2))) * (128 * 128);
    const int rbase = (chunk & 3) * 32;             // position within 128-tile
    #pragma unroll
    for (int i = 0; i < 16; ++i) {
        const int idx  = i * 256 + tid;             // 0..4095
        const int d    = idx >> 5;                  // 0..127
        const int rloc = idx & 31;                  // 0..31
        const int r    = rbase + rloc;              // 0..127
        const int perm = (((r >> 2) ^ ((d >> 2) & 7)) << 2) | (r & 3);
        blk[d * 128 + perm] = tile[rloc][d];
    }
}

__global__ void normT_q_kernel(const float* __restrict__ query) {
    __shared__ float tile[32][132];
    const int h     = blockIdx.y;
    const int chunk = blockIdx.x;       // q' rows chunk*32 .. +31
    const int tid   = threadIdx.x;
    const int w = tid >> 5, l = tid & 31;

    #pragma unroll
    for (int rr = 0; rr < 4; ++rr) {
        const int row = w * 4 + rr;
        const int qp  = chunk * 32 + row;      // 0..4095
        const int b   = qp >> 11;
        const int s   = qp & (SS - 1);
        const size_t grow = (size_t)((b * HH + h) * SS + s);
        float4 v = __ldg(((const float4*)(query + grow * DD)) + l);
        float ss = v.x * v.x + v.y * v.y + v.z * v.z + v.w * v.w;
        #pragma unroll
        for (int o = 16; o > 0; o >>= 1) ss += __shfl_xor_sync(0xffffffffu, ss, o);
        float inv = 1.0f / fmaxf(sqrtf(ss), 1e-11f);
        tile[row][l * 4 + 0] = v.x * inv;
        tile[row][l * 4 + 1] = v.y * inv;
        tile[row][l * 4 + 2] = v.z * inv;
        tile[row][l * 4 + 3] = v.w * inv;
    }
    __syncthreads();

    // write transposed + swizzled into the 32KB tile block (64-wide rows)
    float* blk = g_qt + ((size_t)(h * 64 + (chunk >> 1))) * (128 * 64);
    const int rbase = (chunk & 1) * 32;             // position within 64-tile
    #pragma unroll
    for (int i = 0; i < 16; ++i) {
        const int idx  = i * 256 + tid;             // 0..4095
        const int d    = idx >> 5;                  // 0..127
        const int rloc = idx & 31;                  // 0..31
        const int r    = rbase + rloc;              // 0..63
        const int perm = (((r >> 2) ^ ((d >> 2) & 15)) << 2) | (r & 3);
        blk[d * 64 + perm] = tile[rloc][d];
    }
}

// ---------------------------------------------------------------------------
// Identity tile copies (blocks are pre-transposed + pre-swizzled in global):
// coalesced LDG.128 -> conflict-free STS.128
// ---------------------------------------------------------------------------
__device__ __forceinline__ void copy_64k(const float* __restrict__ src,
                                         float* __restrict__ dst, int tid) {
    #pragma unroll
    for (int i = 0; i < 32; ++i) {
        const int f = i * 128 + tid;                // float4 index 0..4095
        ((float4*)dst)[f] = __ldg((const float4*)src + f);
    }
}
__device__ __forceinline__ void copy_32k(const float* __restrict__ src,
                                         float* __restrict__ dst, int tid) {
    #pragma unroll
    for (int i = 0; i < 16; ++i) {
        const int f = i * 128 + tid;                // float4 index 0..2047
        ((float4*)dst)[f] = __ldg((const float4*)src + f);
    }
}

// Register-resident top-16 insert (static indices after unroll -> no spill)
__device__ __forceinline__ void insert16(float v, int idx,
                                         float tv[16], int ti[16],
                                         float& tmin, int& pmin) {
    #pragma unroll
    for (int j = 0; j < 16; ++j) {
        if (j == pmin) { tv[j] = v; ti[j] = idx; }
    }
    tmin = tv[0]; pmin = 0;
    #pragma unroll
    for (int j = 1; j < 16; ++j) {
        if (tv[j] < tmin) { tmin = tv[j]; pmin = j; }
    }
}

// ---------------------------------------------------------------------------
// Fused kernel (R12 structure; loads are identity copies): per (head, 64-q tile):
//   loop 32 tiles: copy K block -> GEMM (8x8 acc) -> sync -> stage sims into
//   Ks head (stride 129) -> sync -> selection. Then merge, gather, blend.
// ---------------------------------------------------------------------------
__global__ void __launch_bounds__(NTHREADS, 2)
fused_knn_kernel(const float* __restrict__ vmem,
                 const float* __restrict__ outputs,
                 const float* __restrict__ gate,
                 float* __restrict__ out) {
    extern __shared__ float sm[];
    float* Qs = sm;                 // 8192 floats
    float* Ks = sm + 8192;          // 16384 floats (sims alias its head)
    float* Ss = Ks;                 // 64 x 129 sims

    const int h     = blockIdx.y;
    const int qt    = blockIdx.x;
    const int qbase = qt * TQ;
    const int tid   = threadIdx.x;
    const int ty    = tid >> 4;     // 0..7  (rows ty*8..ty*8+7)
    const int tx    = tid & 15;     // 0..15 (cols tx*8..tx*8+7)
    const int srow  = tid >> 1;     // selection row 0..63
    const int shalf = tid & 1;      // selection half (0/1)

    copy_32k(g_qt + ((size_t)(h * 64 + qt)) * (128 * 64), Qs, tid);

    // top-16 state (registers)
    float tv[16]; int ti[16];
    #pragma unroll
    for (int j = 0; j < 16; ++j) { tv[j] = -1e30f; ti[j] = 0; }
    float tmin = -1e30f; int pmin = 0;

    const float* kblocks = g_kt + (size_t)h * 32 * (128 * 128);

    for (int t = 0; t < 32; ++t) {
        __syncthreads();  // prev selection done with Ss(=Ks); Qs ready (1st)
        copy_64k(kblocks + (size_t)t * (128 * 128), Ks, tid);
        __syncthreads();

        float acc[8][8];
        #pragma unroll
        for (int i = 0; i < 8; ++i)
            #pragma unroll
            for (int j = 0; j < 8; ++j) acc[i][j] = 0.0f;

        #pragma unroll 4
        for (int kk = 0; kk < 128; ++kk) {
            int s8  = (kk >> 2) & 7;
            int s16 = (kk >> 2) & 15;
            const float4 a0 = *(const float4*)&Qs[kk * 64  + (((ty * 2)     ^ s16) << 2)];
            const float4 a1 = *(const float4*)&Qs[kk * 64  + (((ty * 2 + 1) ^ s16) << 2)];
            const float4 b0 = *(const float4*)&Ks[kk * 128 + (((tx * 2)     ^ s8)  << 2)];
            const float4 b1 = *(const float4*)&Ks[kk * 128 + (((tx * 2 + 1) ^ s8)  << 2)];
            float a[8] = {a0.x, a0.y, a0.z, a0.w, a1.x, a1.y, a1.z, a1.w};
            float b[8] = {b0.x, b0.y, b0.z, b0.w, b1.x, b1.y, b1.z, b1.w};
            #pragma unroll
            for (int i = 0; i < 8; ++i)
                #pragma unroll
                for (int j = 0; j < 8; ++j) acc[i][j] += a[i] * b[j];
        }
        __syncthreads();  // all GEMM reads of Ks complete before sims overwrite it

        // stage sims into Ks head (stride 129, conflict-free column scans)
        #pragma unroll
        for (int i = 0; i < 8; ++i)
            #pragma unroll
            for (int j = 0; j < 8; ++j)
                Ss[(ty * 8 + i) * 129 + tx * 8 + j] = acc[i][j];
        __syncthreads();

        // selection: thread (srow, shalf) scans 64 candidates
        const float* sp = Ss + srow * 129 + shalf * 64;
        const int base = t * TM + shalf * 64;
        #pragma unroll 4
        for (int c = 0; c < 64; ++c) {
            float v = sp[c];
            if (v > tmin) insert16(v, base + c, tv, ti, tmin, pmin);
        }
    }

    // ---- merge the two halves per row (scratch in Qs region) ----
    __syncthreads();
    float* MV = Qs;                       // 64*32 floats
    int*   MI = (int*)(Qs + 2048);        // 64*32 ints
    {
        int mb = srow * 32 + shalf * 16;
        #pragma unroll
        for (int j = 0; j < 16; ++j) { MV[mb + j] = tv[j]; MI[mb + j] = ti[j]; }
    }
    __syncthreads();

    float* FV = Qs + 4096;                // 64*16 floats
    int*   FI = (int*)(Qs + 5120);        // 64*16 ints
    if (tid < 64) {
        #pragma unroll
        for (int j = 0; j < 16; ++j) { tv[j] = -1e30f; ti[j] = 0; }
        tmin = -1e30f; pmin = 0;
        #pragma unroll 2
        for (int c = 0; c < 32; ++c) {
            float v = MV[tid * 32 + c];
            if (v > tmin) insert16(v, MI[tid * 32 + c], tv, ti, tmin, pmin);
        }
        #pragma unroll
        for (int j = 0; j < 16; ++j) { FV[tid * 16 + j] = tv[j]; FI[tid * 16 + j] = ti[j]; }
    }
    __syncthreads();

    // ---- weighted value gather + gated blend ----
    const int row = tid >> 1;             // 0..63
    const int dh  = (tid & 1) << 6;       // 0 or 64
    float accd[64];
    #pragma unroll
    for (int t = 0; t < 64; ++t) accd[t] = 0.0f;

    const float* vh = vmem + (size_t)h * MM * DD;
    for (int j = 0; j < 16; ++j) {
        float sc = FV[row * 16 + j];
        int   ix = FI[row * 16 + j];
        const float4* vp = (const float4*)(vh + (size_t)ix * DD + dh);
        #pragma unroll
        for (int t = 0; t < 16; ++t) {
            float4 w = __ldg(vp + t);
            accd[4 * t + 0] += sc * w.x;
            accd[4 * t + 1] += sc * w.y;
            accd[4 * t + 2] += sc * w.z;
            accd[4 * t + 3] += sc * w.w;
        }
    }

    // Output flat index == wm flat index (raw reshape); gate head from out layout
    size_t l = ((size_t)(h * QQ + qbase + row)) * DD + dh;
    int hout = (int)((l >> 18) & (HH - 1));     // S*D = 2^18
    float gg = 1.0f / (1.0f + expf(-__ldg(gate + hout)));
    float og = 1.0f - gg;

    const float4* op = (const float4*)(outputs + l);
    float4*       wp = (float4*)(out + l);
    #pragma unroll
    for (int t = 0; t < 16; ++t) {
        float4 o = __ldg(op + t);
        float4 r;
        r.x = gg * accd[4 * t + 0] + og * o.x;
        r.y = gg * accd[4 * t + 1] + og * o.y;
        r.z = gg * accd[4 * t + 2] + og * o.z;
        r.w = gg * accd[4 * t + 3] + og * o.w;
        wp[t] = r;
    }
}

// ---------------------------------------------------------------------------
extern "C" void kernel_launch(void* const* d_in, const int* in_sizes, int n_in,
                              void* d_out, int out_size) {
    // metadata order: inputs, query, key, value, outputs, gate, key_memories, value_memories
    const float* query   = (const float*)d_in[1];
    const float* outputs = (const float*)d_in[4];
    const float* gate    = (const float*)d_in[5];
    const float* kmem    = (const float*)d_in[6];
    const float* vmem    = (const float*)d_in[7];
    float* out = (float*)d_out;

    const int smem_bytes = SMEM_FLOATS * (int)sizeof(float);  // 98304
    cudaFuncSetAttribute(fused_knn_kernel,
                         cudaFuncAttributeMaxDynamicSharedMemorySize, smem_bytes);

    dim3 gk(MM / 32, HH);   // (128, 16)
    dim3 gq(QQ / 32, HH);   // (128, 16)
    normT_k_kernel<<<gk, 256>>>(kmem);
    normT_q_kernel<<<gq, 256>>>(query);

    dim3 grid(QQ / TQ, HH);  // (64, 16) = 1024 CTAs, 2 per SM
    fused_knn_kernel<<<grid, NTHREADS, smem_bytes>>>(vmem, outputs, gate, out);
}

// round 14
// speedup vs baseline: 1.6922x; 1.6922x over previous
#include <cuda_runtime.h>
#include <math.h>
#include <stdint.h>

// Shapes (hardcoded for this problem instance)
#define BB   2
#define HH   16
#define SS   2048
#define DD   128
#define MM   4096          // memories per head
#define QQ   4096          // B*S queries per head

#define TQ   64            // query tile per CTA (occ-2 sizing)
#define TM   128           // memory tile per iteration
#define NTHREADS 128

// SMEM (floats): Qs [d][q] 128x64 @0 (32KB), Ks [d][m] 128x128 @8192 (64KB)
// sims alias into Ks head: 64 rows x stride 129 = 8256 floats (33KB <= 64KB)
#define SMEM_FLOATS (8192 + 16384)

// Scratch: normalized tensors stored TRANSPOSED + PRE-SWIZZLED per tile block:
//   g_kt: [h][mt (32)][d (128)][perm8_d(r) (128)]   64KB blocks
//   g_qt: [h][qt (64)][d (128)][perm16_d(r) (64)]   32KB blocks
// perm8_d(r)  = ((r>>2 ^ ((d>>2)&7 )) << 2) | (r&3)
// perm16_d(r) = ((r>>2 ^ ((d>>2)&15)) << 2) | (r&3)
__device__ float g_kt[HH * MM * DD];
__device__ float g_qt[HH * QQ * DD];

#define CP16(dst, src) \
    asm volatile("cp.async.cg.shared.global [%0], [%1], 16;" :: "r"(dst), "l"(src))
#define CP_COMMIT() asm volatile("cp.async.commit_group;" ::: "memory")
#define CP_WAIT0()  asm volatile("cp.async.wait_group 0;" ::: "memory")

__device__ __forceinline__ uint32_t smem_u32(const void* p) {
    uint32_t a;
    asm("{ .reg .u64 t; cvta.to.shared.u64 t, %1; cvt.u32.u64 %0, t; }" : "=r"(a) : "l"(p));
    return a;
}

// ---------------------------------------------------------------------------
// Norm + transpose + swizzle kernels: block = (h, 32-row chunk), 256 threads.
// Row normalization arithmetic identical to R1 (warp-per-row, shfl reduce).
// ---------------------------------------------------------------------------
__global__ void normT_k_kernel(const float* __restrict__ km) {
    __shared__ float tile[32][132];
    const int h     = blockIdx.y;
    const int chunk = blockIdx.x;       // rows chunk*32 .. +31
    const int tid   = threadIdx.x;
    const int w = tid >> 5, l = tid & 31;

    #pragma unroll
    for (int rr = 0; rr < 4; ++rr) {
        const int row = w * 4 + rr;     // 0..31
        const size_t grow = (size_t)(h * MM + chunk * 32 + row);
        float4 v = __ldg(((const float4*)(km + grow * DD)) + l);
        float ss = v.x * v.x + v.y * v.y + v.z * v.z + v.w * v.w;
        #pragma unroll
        for (int o = 16; o > 0; o >>= 1) ss += __shfl_xor_sync(0xffffffffu, ss, o);
        float inv = 1.0f / fmaxf(sqrtf(ss), 1e-11f);
        tile[row][l * 4 + 0] = v.x * inv;
        tile[row][l * 4 + 1] = v.y * inv;
        tile[row][l * 4 + 2] = v.z * inv;
        tile[row][l * 4 + 3] = v.w * inv;
    }
    __syncthreads();

    // write transposed + swizzled into the 64KB tile block
    float* blk = g_kt + ((size_t)(h * 32 + (chunk >> 2))) * (128 * 128);
    const int rbase = (chunk & 3) * 32;             // position within 128-tile
    #pragma unroll
    for (int i = 0; i < 16; ++i) {
        const int idx  = i * 256 + tid;             // 0..4095
        const int d    = idx >> 5;                  // 0..127
        const int rloc = idx & 31;                  // 0..31
        const int r    = rbase + rloc;              // 0..127
        const int perm = (((r >> 2) ^ ((d >> 2) & 7)) << 2) | (r & 3);
        blk[d * 128 + perm] = tile[rloc][d];
    }
}

__global__ void normT_q_kernel(const float* __restrict__ query) {
    __shared__ float tile[32][132];
    const int h     = blockIdx.y;
    const int chunk = blockIdx.x;       // q' rows chunk*32 .. +31
    const int tid   = threadIdx.x;
    const int w = tid >> 5, l = tid & 31;

    #pragma unroll
    for (int rr = 0; rr < 4; ++rr) {
        const int row = w * 4 + rr;
        const int qp  = chunk * 32 + row;      // 0..4095
        const int b   = qp >> 11;
        const int s   = qp & (SS - 1);
        const size_t grow = (size_t)((b * HH + h) * SS + s);
        float4 v = __ldg(((const float4*)(query + grow * DD)) + l);
        float ss = v.x * v.x + v.y * v.y + v.z * v.z + v.w * v.w;
        #pragma unroll
        for (int o = 16; o > 0; o >>= 1) ss += __shfl_xor_sync(0xffffffffu, ss, o);
        float inv = 1.0f / fmaxf(sqrtf(ss), 1e-11f);
        tile[row][l * 4 + 0] = v.x * inv;
        tile[row][l * 4 + 1] = v.y * inv;
        tile[row][l * 4 + 2] = v.z * inv;
        tile[row][l * 4 + 3] = v.w * inv;
    }
    __syncthreads();

    // write transposed + swizzled into the 32KB tile block (64-wide rows)
    float* blk = g_qt + ((size_t)(h * 64 + (chunk >> 1))) * (128 * 64);
    const int rbase = (chunk & 1) * 32;             // position within 64-tile
    #pragma unroll
    for (int i = 0; i < 16; ++i) {
        const int idx  = i * 256 + tid;             // 0..4095
        const int d    = idx >> 5;                  // 0..127
        const int rloc = idx & 31;                  // 0..31
        const int r    = rbase + rloc;              // 0..63
        const int perm = (((r >> 2) ^ ((d >> 2) & 15)) << 2) | (r & 3);
        blk[d * 64 + perm] = tile[rloc][d];
    }
}

// Register-resident top-16 insert (static indices after unroll -> no spill)
__device__ __forceinline__ void insert16(float v, int idx,
                                         float tv[16], int ti[16],
                                         float& tmin, int& pmin) {
    #pragma unroll
    for (int j = 0; j < 16; ++j) {
        if (j == pmin) { tv[j] = v; ti[j] = idx; }
    }
    tmin = tv[0]; pmin = 0;
    #pragma unroll
    for (int j = 1; j < 16; ++j) {
        if (tv[j] < tmin) { tmin = tv[j]; pmin = j; }
    }
}

// ---------------------------------------------------------------------------
// Fused kernel (R12 structure; tile loads via cp.async identity DMA):
// per (head, 64-q tile): loop 32 tiles: cp.async K block -> GEMM (8x8 acc) ->
// sync -> stage sims into Ks head (stride 129) -> sync -> selection.
// Then merge, gather, blend.
// ---------------------------------------------------------------------------
__global__ void __launch_bounds__(NTHREADS, 2)
fused_knn_kernel(const float* __restrict__ vmem,
                 const float* __restrict__ outputs,
                 const float* __restrict__ gate,
                 float* __restrict__ out) {
    extern __shared__ float sm[];
    float* Qs = sm;                 // 8192 floats
    float* Ks = sm + 8192;          // 16384 floats (sims alias its head)
    float* Ss = Ks;                 // 64 x 129 sims

    const uint32_t sb   = smem_u32(sm);
    const uint32_t sb_k = sb + 8192 * 4;

    const int h     = blockIdx.y;
    const int qt    = blockIdx.x;
    const int qbase = qt * TQ;
    const int tid   = threadIdx.x;
    const int ty    = tid >> 4;     // 0..7  (rows ty*8..ty*8+7)
    const int tx    = tid & 15;     // 0..15 (cols tx*8..tx*8+7)
    const int srow  = tid >> 1;     // selection row 0..63
    const int shalf = tid & 1;      // selection half (0/1)

    // Q tile: identity cp.async (pre-swizzled block in global)
    {
        const float* qsrc = g_qt + ((size_t)(h * 64 + qt)) * (128 * 64);
        #pragma unroll
        for (int i = 0; i < 16; ++i) {
            const int f = i * 128 + tid;           // float4 index 0..2047
            CP16(sb + f * 16, qsrc + f * 4);
        }
        CP_COMMIT();
    }

    // top-16 state (registers)
    float tv[16]; int ti[16];
    #pragma unroll
    for (int j = 0; j < 16; ++j) { tv[j] = -1e30f; ti[j] = 0; }
    float tmin = -1e30f; int pmin = 0;

    const float* kblocks = g_kt + (size_t)h * 32 * (128 * 128);

    for (int t = 0; t < 32; ++t) {
        __syncthreads();  // prev selection done with Ss(=Ks); Qs in flight (1st)
        {
            const float* ksrc = kblocks + (size_t)t * (128 * 128);
            #pragma unroll
            for (int i = 0; i < 32; ++i) {
                const int f = i * 128 + tid;       // float4 index 0..4095
                CP16(sb_k + f * 16, ksrc + f * 4);
            }
            CP_COMMIT();
        }
        CP_WAIT0();       // K tile (and Q on first iter) complete for this thread
        __syncthreads();  // publish to all threads

        float acc[8][8];
        #pragma unroll
        for (int i = 0; i < 8; ++i)
            #pragma unroll
            for (int j = 0; j < 8; ++j) acc[i][j] = 0.0f;

        #pragma unroll 4
        for (int kk = 0; kk < 128; ++kk) {
            int s8  = (kk >> 2) & 7;
            int s16 = (kk >> 2) & 15;
            const float4 a0 = *(const float4*)&Qs[kk * 64  + (((ty * 2)     ^ s16) << 2)];
            const float4 a1 = *(const float4*)&Qs[kk * 64  + (((ty * 2 + 1) ^ s16) << 2)];
            const float4 b0 = *(const float4*)&Ks[kk * 128 + (((tx * 2)     ^ s8)  << 2)];
            const float4 b1 = *(const float4*)&Ks[kk * 128 + (((tx * 2 + 1) ^ s8)  << 2)];
            float a[8] = {a0.x, a0.y, a0.z, a0.w, a1.x, a1.y, a1.z, a1.w};
            float b[8] = {b0.x, b0.y, b0.z, b0.w, b1.x, b1.y, b1.z, b1.w};
            #pragma unroll
            for (int i = 0; i < 8; ++i)
                #pragma unroll
                for (int j = 0; j < 8; ++j) acc[i][j] += a[i] * b[j];
        }
        __syncthreads();  // all GEMM reads of Ks complete before sims overwrite it

        // stage sims into Ks head (stride 129, conflict-free column scans)
        #pragma unroll
        for (int i = 0; i < 8; ++i)
            #pragma unroll
            for (int j = 0; j < 8; ++j)
                Ss[(ty * 8 + i) * 129 + tx * 8 + j] = acc[i][j];
        __syncthreads();

        // selection: thread (srow, shalf) scans 64 candidates
        const float* sp = Ss + srow * 129 + shalf * 64;
        const int base = t * TM + shalf * 64;
        #pragma unroll 4
        for (int c = 0; c < 64; ++c) {
            float v = sp[c];
            if (v > tmin) insert16(v, base + c, tv, ti, tmin, pmin);
        }
    }

    // ---- merge the two halves per row (scratch in Qs region) ----
    __syncthreads();
    float* MV = Qs;                       // 64*32 floats
    int*   MI = (int*)(Qs + 2048);        // 64*32 ints
    {
        int mb = srow * 32 + shalf * 16;
        #pragma unroll
        for (int j = 0; j < 16; ++j) { MV[mb + j] = tv[j]; MI[mb + j] = ti[j]; }
    }
    __syncthreads();

    float* FV = Qs + 4096;                // 64*16 floats
    int*   FI = (int*)(Qs + 5120);        // 64*16 ints
    if (tid < 64) {
        #pragma unroll
        for (int j = 0; j < 16; ++j) { tv[j] = -1e30f; ti[j] = 0; }
        tmin = -1e30f; pmin = 0;
        #pragma unroll 2
        for (int c = 0; c < 32; ++c) {
            float v = MV[tid * 32 + c];
            if (v > tmin) insert16(v, MI[tid * 32 + c], tv, ti, tmin, pmin);
        }
        #pragma unroll
        for (int j = 0; j < 16; ++j) { FV[tid * 16 + j] = tv[j]; FI[tid * 16 + j] = ti[j]; }
    }
    __syncthreads();

    // ---- weighted value gather + gated blend ----
    const int row = tid >> 1;             // 0..63
    const int dh  = (tid & 1) << 6;       // 0 or 64
    float accd[64];
    #pragma unroll
    for (int t = 0; t < 64; ++t) accd[t] = 0.0f;

    const float* vh = vmem + (size_t)h * MM * DD;
    for (int j = 0; j < 16; ++j) {
        float sc = FV[row * 16 + j];
        int   ix = FI[row * 16 + j];
        const float4* vp = (const float4*)(vh + (size_t)ix * DD + dh);
        #pragma unroll
        for (int t = 0; t < 16; ++t) {
            float4 w = __ldg(vp + t);
            accd[4 * t + 0] += sc * w.x;
            accd[4 * t + 1] += sc * w.y;
            accd[4 * t + 2] += sc * w.z;
            accd[4 * t + 3] += sc * w.w;
        }
    }

    // Output flat index == wm flat index (raw reshape); gate head from out layout
    size_t l = ((size_t)(h * QQ + qbase + row)) * DD + dh;
    int hout = (int)((l >> 18) & (HH - 1));     // S*D = 2^18
    float gg = 1.0f / (1.0f + expf(-__ldg(gate + hout)));
    float og = 1.0f - gg;

    const float4* op = (const float4*)(outputs + l);
    float4*       wp = (float4*)(out + l);
    #pragma unroll
    for (int t = 0; t < 16; ++t) {
        float4 o = __ldg(op + t);
        float4 r;
        r.x = gg * accd[4 * t + 0] + og * o.x;
        r.y = gg * accd[4 * t + 1] + og * o.y;
        r.z = gg * accd[4 * t + 2] + og * o.z;
        r.w = gg * accd[4 * t + 3] + og * o.w;
        wp[t] = r;
    }
}

// ---------------------------------------------------------------------------
extern "C" void kernel_launch(void* const* d_in, const int* in_sizes, int n_in,
                              void* d_out, int out_size) {
    // metadata order: inputs, query, key, value, outputs, gate, key_memories, value_memories
    const float* query   = (const float*)d_in[1];
    const float* outputs = (const float*)d_in[4];
    const float* gate    = (const float*)d_in[5];
    const float* kmem    = (const float*)d_in[6];
    const float* vmem    = (const float*)d_in[7];
    float* out = (float*)d_out;

    const int smem_bytes = SMEM_FLOATS * (int)sizeof(float);  // 98304
    cudaFuncSetAttribute(fused_knn_kernel,
                         cudaFuncAttributeMaxDynamicSharedMemorySize, smem_bytes);

    dim3 gk(MM / 32, HH);   // (128, 16)
    dim3 gq(QQ / 32, HH);   // (128, 16)
    normT_k_kernel<<<gk, 256>>>(kmem);
    normT_q_kernel<<<gq, 256>>>(query);

    dim3 grid(QQ / TQ, HH);  // (64, 16) = 1024 CTAs, 2 per SM
    fused_knn_kernel<<<grid, NTHREADS, smem_bytes>>>(vmem, outputs, gate, out);
}